// round 12
// baseline (speedup 1.0000x reference)
#include <cuda_runtime.h>
#include <cuda_fp16.h>

// PairwisePotential1 — column-strip streaming, stride-4 half2 pairing,
// 8 cols x 4 rows per thread; __launch_bounds__(256,6) forces 6 blocks/SM
// (regs <= 42) for latency hiding. Epilogue restructured to shrink live set.
// Pixel pairs are (p, p+4): every pack is (v_m, v_m+4) = one F2FP, no PRMT.
// first = 1 + sum_{8 fwd offsets} exp2(-(s*diff)^2 + L), s = sqrt(0.5*log2e),
// L = K*d, K = -0.5*log2(e), d in {1, sqrt2}. Zero padding.
// out = w1 * first/9 + w2 * (4+4*sqrt2)/9.

#define S 128
#define SS (S * S)
#define FULLM 0xFFFFFFFFu

struct Pk { __half2 p[6]; };   // (v_m, v_{m+4}), m = 0..5 ; v_0/v_9 are halo

__device__ __forceinline__ __half2 eterm(__half2 cs, __half2 n,
                                         __half2 LL, __half2 Sn) {
    __half2 ds = __hfma2(n, Sn, cs);                 // s*(c - n)
    return h2exp2(__hfma2(__hneg2(ds), ds, LL));     // exp2(L - ds^2)
}

__device__ __forceinline__ void loadrow(Pk& P, const float* rp, bool valid, int sl) {
    float4 A = make_float4(0.f, 0.f, 0.f, 0.f);
    float4 B = make_float4(0.f, 0.f, 0.f, 0.f);
    if (valid) { A = *(const float4*)rp; B = *(const float4*)(rp + 4); }
    float v0 = __shfl_up_sync(FULLM, B.w, 1, 16);    // col base-1 from left lane
    float v9 = __shfl_down_sync(FULLM, A.x, 1, 16);  // col base+8 from right lane
    if (sl == 0)  v0 = 0.f;
    if (sl == 15) v9 = 0.f;
    P.p[0] = __floats2half2_rn(v0,  A.w);
    P.p[1] = __floats2half2_rn(A.x, B.x);
    P.p[2] = __floats2half2_rn(A.y, B.y);
    P.p[3] = __floats2half2_rn(A.z, B.z);
    P.p[4] = __floats2half2_rn(A.w, B.w);
    P.p[5] = __floats2half2_rn(B.x, v9);
}

__device__ __forceinline__ void step(const Pk& A, const Pk& B, const Pk& C,
                                     const float* w1p, const float* w2p, float* op,
                                     __half2 Sp, __half2 Sn, __half2 L1h, __half2 L2h,
                                     __half2 ONEh) {
    const float INV9   = 1.0f / 9.0f;
    const float SECOND = (4.0f + 4.0f * 1.41421356237309504880f) / 9.0f;

    // Compute the 4 pixel-pairs; consume each pair's result immediately into
    // per-half staging to keep the live f32 set small.
    float lo[4], hi[4];
#pragma unroll
    for (int p = 0; p < 4; p++) {
        __half2 cs = __hmul2(Sp, A.p[p]);            // prescaled centers
        __half2 a = __hadd2(ONEh, eterm(cs, A.p[p + 1], L1h, Sn));
        a = __hadd2(a, eterm(cs, A.p[p + 2], L1h, Sn));
        a = __hadd2(a, eterm(cs, B.p[p],     L1h, Sn));
        a = __hadd2(a, eterm(cs, C.p[p],     L1h, Sn));
        __half2 b =    eterm(cs, B.p[p + 1], L2h, Sn);
        b = __hadd2(b, eterm(cs, B.p[p + 2], L2h, Sn));
        b = __hadd2(b, eterm(cs, C.p[p + 1], L2h, Sn));
        b = __hadd2(b, eterm(cs, C.p[p + 2], L2h, Sn));
        float2 ff = __half22float2(__hadd2(a, b));
        lo[p] = ff.x * INV9;                          // px p
        hi[p] = ff.y * INV9;                          // px p+4
    }
    {   // first half: cols 0..3
        float4 w1v = *(const float4*)w1p;
        float4 w2v = *(const float4*)w2p;
        float4 o;
        o.x = fmaf(w1v.x, lo[0], w2v.x * SECOND);
        o.y = fmaf(w1v.y, lo[1], w2v.y * SECOND);
        o.z = fmaf(w1v.z, lo[2], w2v.z * SECOND);
        o.w = fmaf(w1v.w, lo[3], w2v.w * SECOND);
        *(float4*)op = o;
    }
    {   // second half: cols 4..7
        float4 w1v = *(const float4*)(w1p + 4);
        float4 w2v = *(const float4*)(w2p + 4);
        float4 o;
        o.x = fmaf(w1v.x, hi[0], w2v.x * SECOND);
        o.y = fmaf(w1v.y, hi[1], w2v.y * SECOND);
        o.z = fmaf(w1v.z, hi[2], w2v.z * SECOND);
        o.w = fmaf(w1v.w, hi[3], w2v.w * SECOND);
        *(float4*)(op + 4) = o;
    }
}

__global__ __launch_bounds__(256, 6) void pp_kernel(
    const float* __restrict__ x,
    const float* __restrict__ w1,
    const float* __restrict__ w2,
    float* __restrict__ out)
{
    int t  = blockIdx.x * blockDim.x + threadIdx.x;
    int sl = threadIdx.x & 15;          // strip lane within 16-wide shuffle segment
    int g  = (t >> 4) & 31;             // rowgroup: rows 4g .. 4g+3
    int bc = t >> 9;                    // b*C + c
    int c  = bc & 63;
    int x0 = sl << 3;                   // column base (8 cols per thread)
    int r0 = g << 2;

    const float Kf = -0.5f * 1.44269504088896340736f;
    const float sF = 0.84933300468f;                       // sqrt(0.5*log2e)
    const __half2 Sp  = __float2half2_rn(sF);
    const __half2 Sn  = __float2half2_rn(-sF);
    const __half2 L1h = __float2half2_rn(Kf);                            // d=1
    const __half2 L2h = __float2half2_rn(Kf * 1.41421356237309504880f);  // d=sqrt2
    const __half2 ONEh = __float2half2_rn(1.0f);

    const float* xbase = x   + (size_t)bc * SS + r0 * S + x0;
    const float* w1p   = w1  + (size_t)c  * SS + r0 * S + x0;
    const float* w2p   = w2  + (size_t)c  * SS + r0 * S + x0;
    float*       op    = out + (size_t)bc * SS + r0 * S + x0;

    Pk P0, P1, P2;
    loadrow(P0, xbase - S,     (g > 0), sl);   // row r0-1 (zero for g==0)
    loadrow(P1, xbase,         true,    sl);   // row r0
    loadrow(P2, xbase + S,     true,    sl);   // row r0+1 (r0+1 <= 125)

#define ST(A,B,C,K) step(A, B, C, w1p + (K)*S, w2p + (K)*S, op + (K)*S, \
                         Sp, Sn, L1h, L2h, ONEh);

    ST(P0, P1, P2, 0)
    loadrow(P0, xbase + 2 * S, true, sl);          ST(P1, P2, P0, 1)
    loadrow(P1, xbase + 3 * S, true, sl);          ST(P2, P0, P1, 2)
    loadrow(P2, xbase + 4 * S, (g < 31), sl);      ST(P0, P1, P2, 3)
#undef ST
}

extern "C" void kernel_launch(void* const* d_in, const int* in_sizes, int n_in,
                              void* d_out, int out_size)
{
    const float* x  = (const float*)d_in[0];
    const float* w1 = (const float*)d_in[1];
    const float* w2 = (const float*)d_in[2];
    float* out = (float*)d_out;

    // 8 cols x 4 rows = 32 px per thread
    int total = out_size >> 5;
    int threads = 256;
    int blocks = (total + threads - 1) / threads;
    pp_kernel<<<blocks, threads>>>(x, w1, w2, out);
}

// round 13
// speedup vs baseline: 1.1035x; 1.1035x over previous
#include <cuda_runtime.h>
#include <cuda_fp16.h>

// PairwisePotential1 — warp-per-row coalesced (R9 family), 4 output rows per
// thread with 3-buffer row rotation: 6 row loads per 4 output rows.
// Lane l covers cols 4l..4l+3. Packs in half domain: 2 F2FP + packed shuffle
// + 3 PRMT per row. 2-op prescaled TERM + f16x2 EX2; A/B accs merged in half.
// first = 1 + sum_{8 fwd offsets} exp2(-(s*diff)^2 + L), s = sqrt(0.5*log2e),
// L = K*d, K = -0.5*log2(e), d in {1, sqrt2}. Zero padding.
// out = w1 * first/9 + w2 * (4+4*sqrt2)/9.

#define S 128
#define SS (S * S)
#define FULLM 0xFFFFFFFFu

__device__ __forceinline__ __half2 H2(unsigned u) {
    return *reinterpret_cast<__half2*>(&u);
}
__device__ __forceinline__ unsigned U2(__half2 h) {
    return *reinterpret_cast<unsigned*>(&h);
}

struct Row { unsigned h01, h12, h23, h34, h45; };  // (v0,v1)..(v4,v5), v_k = col 4l-1+k

__device__ __forceinline__ __half2 eterm(__half2 cs, unsigned n,
                                         __half2 LL, __half2 Sn) {
    __half2 ds = __hfma2(H2(n), Sn, cs);             // s*(c - n)
    return h2exp2(__hfma2(__hneg2(ds), ds, LL));     // exp2(L - ds^2)
}

__device__ __forceinline__ void loadrow(Row& RW, const float* rp, bool ok, int lane) {
    float4 m = make_float4(0.f, 0.f, 0.f, 0.f);
    if (ok) m = *(const float4*)rp;
    unsigned p12 = U2(__floats2half2_rn(m.x, m.y));
    unsigned p34 = U2(__floats2half2_rn(m.z, m.w));
    unsigned nb = __shfl_up_sync(FULLM, p34, 1);
    unsigned nd = __shfl_down_sync(FULLM, p12, 1);
    if (lane == 0)  nb = 0u;
    if (lane == 31) nd = 0u;
    RW.h12 = p12; RW.h34 = p34;
    RW.h01 = __byte_perm(nb,  p12, 0x5432);
    RW.h23 = __byte_perm(p12, p34, 0x5432);
    RW.h45 = __byte_perm(p34, nd,  0x5432);
}

__device__ __forceinline__ void outrow(const Row& R0, const Row& R1, const Row& R2,
                                       const float* w1p, const float* w2p, float* op,
                                       __half2 Sp, __half2 Sn,
                                       __half2 L1h, __half2 L2h, __half2 ONEh) {
    // pair0 = px cols 4l,4l+1 ; pair1 = px cols 4l+2,4l+3
    __half2 cs0 = __hmul2(Sp, H2(R0.h01));
    __half2 a0 = __hadd2(ONEh, eterm(cs0, R0.h12, L1h, Sn));
    a0 = __hadd2(a0, eterm(cs0, R0.h23, L1h, Sn));
    a0 = __hadd2(a0, eterm(cs0, R1.h01, L1h, Sn));
    a0 = __hadd2(a0, eterm(cs0, R2.h01, L1h, Sn));
    __half2 b0 =     eterm(cs0, R1.h12, L2h, Sn);
    b0 = __hadd2(b0, eterm(cs0, R1.h23, L2h, Sn));
    b0 = __hadd2(b0, eterm(cs0, R2.h12, L2h, Sn));
    b0 = __hadd2(b0, eterm(cs0, R2.h23, L2h, Sn));

    __half2 cs1 = __hmul2(Sp, H2(R0.h23));
    __half2 a1 = __hadd2(ONEh, eterm(cs1, R0.h34, L1h, Sn));
    a1 = __hadd2(a1, eterm(cs1, R0.h45, L1h, Sn));
    a1 = __hadd2(a1, eterm(cs1, R1.h23, L1h, Sn));
    a1 = __hadd2(a1, eterm(cs1, R2.h23, L1h, Sn));
    __half2 b1 =     eterm(cs1, R1.h34, L2h, Sn);
    b1 = __hadd2(b1, eterm(cs1, R1.h45, L2h, Sn));
    b1 = __hadd2(b1, eterm(cs1, R2.h34, L2h, Sn));
    b1 = __hadd2(b1, eterm(cs1, R2.h45, L2h, Sn));

    float2 f0 = __half22float2(__hadd2(a0, b0));
    float2 f1 = __half22float2(__hadd2(a1, b1));

    const float INV9   = 1.0f / 9.0f;
    const float SECOND = (4.0f + 4.0f * 1.41421356237309504880f) / 9.0f;
    float4 w1v = *(const float4*)w1p;
    float4 w2v = *(const float4*)w2p;
    float4 o;
    o.x = fmaf(w1v.x, f0.x * INV9, w2v.x * SECOND);
    o.y = fmaf(w1v.y, f0.y * INV9, w2v.y * SECOND);
    o.z = fmaf(w1v.z, f1.x * INV9, w2v.z * SECOND);
    o.w = fmaf(w1v.w, f1.y * INV9, w2v.w * SECOND);
    *(float4*)op = o;
}

__global__ __launch_bounds__(256) void pp_kernel(
    const float* __restrict__ x,
    const float* __restrict__ w1,
    const float* __restrict__ w2,
    float* __restrict__ out)
{
    int t    = blockIdx.x * blockDim.x + threadIdx.x;
    int lane = t & 31;
    int w    = t >> 5;              // warp id
    int g    = w & 31;              // rowgroup: output rows 4g..4g+3
    int bc   = w >> 5;              // b*C + c
    int c    = bc & 63;
    int x0   = lane << 2;
    int y0   = g << 2;

    const float Kf = -0.5f * 1.44269504088896340736f;
    const float sF = 0.84933300468f;                       // sqrt(0.5*log2e)
    const __half2 Sp  = __float2half2_rn(sF);
    const __half2 Sn  = __float2half2_rn(-sF);
    const __half2 L1h = __float2half2_rn(Kf);                            // d=1
    const __half2 L2h = __float2half2_rn(Kf * 1.41421356237309504880f);  // d=sqrt2
    const __half2 ONEh = __float2half2_rn(1.0f);

    const float* xbase = x   + (size_t)bc * SS + y0 * S + x0;
    const float* w1p   = w1  + (size_t)c  * SS + y0 * S + x0;
    const float* w2p   = w2  + (size_t)c  * SS + y0 * S + x0;
    float*       op    = out + (size_t)bc * SS + y0 * S + x0;

    Row R0, R1, R2;
    loadrow(R0, xbase - S,     (g > 0), lane);   // orig row y0-1
    loadrow(R1, xbase,         true,    lane);   // orig row y0
    loadrow(R2, xbase + S,     true,    lane);   // orig row y0+1  (<= 125+1)

#define OROW(A,B,C,K) outrow(A, B, C, w1p + (K)*S, w2p + (K)*S, op + (K)*S, \
                             Sp, Sn, L1h, L2h, ONEh);

    OROW(R0, R1, R2, 0)
    loadrow(R0, xbase + 2 * S, true, lane);        OROW(R1, R2, R0, 1)
    loadrow(R1, xbase + 3 * S, true, lane);        OROW(R2, R0, R1, 2)
    loadrow(R2, xbase + 4 * S, (g < 31), lane);    OROW(R0, R1, R2, 3)
#undef OROW
}

extern "C" void kernel_launch(void* const* d_in, const int* in_sizes, int n_in,
                              void* d_out, int out_size)
{
    const float* x  = (const float*)d_in[0];
    const float* w1 = (const float*)d_in[1];
    const float* w2 = (const float*)d_in[2];
    float* out = (float*)d_out;

    // 16 px per thread (4 rows x 4 cols), warp covers 128 cols x 4 rows
    int total = out_size >> 4;
    int threads = 256;
    int blocks = (total + threads - 1) / threads;
    pp_kernel<<<blocks, threads>>>(x, w1, w2, out);
}